// round 15
// baseline (speedup 1.0000x reference)
#include <cuda_runtime.h>
#include <cstdint>

#define NN 50000
#define NR 50048      // 391 * 128
#define EE 800000
#define FIN 128
#define HH 4
#define FO 64
#define NOUT 256

#define NODE_BLKS 6250   // 50000 warps @ 8 warps/block
#define HIST_BLKS 782    // ceil((EE/4)/256)
#define PREP_BLKS 128    // 32768/256
#define SCAN_BLKS 49     // ceil(NN/1024)
#define AGG_BLKS 592     // 4 blocks/SM x 148 SMs, persistent work-stealing

// ---- static scratch ----
__device__ float g_z[(size_t)NR * 512];   // aggregated features [n][h][128] fp32
__device__ float g_wsh[NOUT * FIN];       // W tf32-hi
__device__ float g_wsl[NOUT * FIN];       // W tf32-lo
__device__ float g_el2[NN * HH];
__device__ float g_wc[HH * FIN];
__device__ int   g_counts[NN];            // zeroed inside k_agg steal loop
__device__ int   g_offsets[NN + 1];
__device__ int   g_cursor[NN];
__device__ int   g_csr_src[EE];
__device__ int   g_partial[64];           // scan block totals
__device__ int   g_flag[64];              // scan publish flags (zeroed by k_front)
__device__ int   g_work;                  // agg work-steal counter (reset by k_front)

// ---- tf32 helpers ----
__device__ __forceinline__ float tf32_rna(float x) {
    uint32_t r;
    asm("cvt.rna.tf32.f32 %0, %1;" : "=r"(r) : "f"(x));
    return __uint_as_float(r);
}
__device__ __forceinline__ void mma_tf32(float& d0, float& d1, float& d2, float& d3,
                                         uint32_t a0, uint32_t a1, uint32_t a2, uint32_t a3,
                                         uint32_t b0, uint32_t b1) {
    asm("mma.sync.aligned.m16n8k8.row.col.f32.tf32.tf32.f32 "
        "{%0,%1,%2,%3}, {%4,%5,%6,%7}, {%8,%9}, {%0,%1,%2,%3};"
        : "+f"(d0), "+f"(d1), "+f"(d2), "+f"(d3)
        : "r"(a0), "r"(a1), "r"(a2), "r"(a3), "r"(b0), "r"(b1));
}

// ---------------- fused front: node-el2 | hist | W-split+wc+flag/counter-reset ----------------
__global__ void __launch_bounds__(256)
k_front(const float* __restrict__ feat,
        const int* __restrict__ dst,
        const float* __restrict__ al, const float* __restrict__ ar,
        const float* __restrict__ al1, const float* __restrict__ ar1,
        const float* __restrict__ W) {
    int b = blockIdx.x;
    int tid = threadIdx.x;

    if (b < NODE_BLKS) {
        int warp = (b * 256 + tid) >> 5;
        int lane = tid & 31;
        if (warp >= NN) return;
        float4 f = *(const float4*)(feat + warp * FIN + lane * 4);
        float q0 = f.x * f.x, q1 = f.y * f.y, q2 = f.z * f.z, q3 = f.w * f.w;
        float pl[4];
#pragma unroll
        for (int h = 0; h < 4; h++) {
            float4 a = *(const float4*)(al1 + h * FIN + lane * 4);
            pl[h] = q0 * a.x * a.x + q1 * a.y * a.y + q2 * a.z * a.z + q3 * a.w * a.w;
        }
#pragma unroll
        for (int off = 16; off; off >>= 1) {
#pragma unroll
            for (int h = 0; h < 4; h++)
                pl[h] += __shfl_xor_sync(0xffffffffu, pl[h], off);
        }
        if (lane == 0)
            *(float4*)(g_el2 + warp * 4) = make_float4(pl[0], pl[1], pl[2], pl[3]);
    } else if (b < NODE_BLKS + HIST_BLKS) {
        int e4 = ((b - NODE_BLKS) * 256 + tid) * 4;
        if (e4 < EE) {
            int4 d4 = *(const int4*)(dst + e4);
            atomicAdd(&g_counts[d4.x], 1);
            atomicAdd(&g_counts[d4.y], 1);
            atomicAdd(&g_counts[d4.z], 1);
            atomicAdd(&g_counts[d4.w], 1);
        }
    } else {
        int i = (b - NODE_BLKS - HIST_BLKS) * 256 + tid;   // 0..32767
        float w = W[i];
        float hi = tf32_rna(w);
        g_wsh[i] = hi;
        g_wsl[i] = tf32_rna(w - hi);
        if (i < HH * FIN) g_wc[i] = al[i] * ar[i] - 2.0f * al1[i] * ar1[i];
        if (i < 64) g_flag[i] = 0;   // reset scan flags
        if (i == 64) g_work = 0;     // reset agg work counter
    }
}

// ---------------- single-kernel scan (decoupled lookback; 49 blocks, all wave-1) ----------------
__global__ void __launch_bounds__(1024)
k_scan() {
    __shared__ int wsum[32];
    __shared__ int s_prefix;
    int tid = threadIdx.x;
    int b = blockIdx.x;
    int t = b * 1024 + tid;
    int lane = tid & 31, wid = tid >> 5;
    int cnt = (t < NN) ? g_counts[t] : 0;
    int x = cnt;
#pragma unroll
    for (int off = 1; off < 32; off <<= 1) {
        int y = __shfl_up_sync(0xffffffffu, x, off);
        if (lane >= off) x += y;
    }
    if (lane == 31) wsum[wid] = x;
    __syncthreads();
    if (wid == 0) {
        int ws = wsum[lane];
#pragma unroll
        for (int off = 1; off < 32; off <<= 1) {
            int y = __shfl_up_sync(0xffffffffu, ws, off);
            if (lane >= off) ws += y;
        }
        wsum[lane] = ws;
    }
    __syncthreads();
    if (wid > 0) x += wsum[wid - 1];
    if (tid == 1023) {
        *((volatile int*)g_partial + b) = x;
        __threadfence();
        atomicExch(&g_flag[b], 1);
    }
    if (wid == 0) {
        int sum = 0;
        for (int i = lane; i < b; i += 32) {
            while (atomicAdd(&g_flag[i], 0) == 0) { }
            sum += *((volatile int*)g_partial + i);
        }
#pragma unroll
        for (int off = 16; off; off >>= 1)
            sum += __shfl_xor_sync(0xffffffffu, sum, off);
        if (lane == 0) s_prefix = sum;
    }
    __syncthreads();
    int inc = x + s_prefix;
    if (t < NN) {
        g_offsets[t + 1] = inc;
        g_cursor[t] = inc - cnt;
    }
    if (t == 0) g_offsets[0] = 0;
}

__global__ void k_scatter(const int* __restrict__ src, const int* __restrict__ dst) {
    int e4 = (blockIdx.x * blockDim.x + threadIdx.x) * 4;
    if (e4 < EE) {
        int4 s4 = *(const int4*)(src + e4);
        int4 d4 = *(const int4*)(dst + e4);
        int p0 = atomicAdd(&g_cursor[d4.x], 1); g_csr_src[p0] = s4.x;
        int p1 = atomicAdd(&g_cursor[d4.y], 1); g_csr_src[p1] = s4.y;
        int p2 = atomicAdd(&g_cursor[d4.z], 1); g_csr_src[p2] = s4.z;
        int p3 = atomicAdd(&g_cursor[d4.w], 1); g_csr_src[p3] = s4.w;
    }
}

// ---------------- fused score + softmax + agg, persistent work-stealing ----------------
// One warp per node via global atomic queue: light-node warps immediately pull
// more work, eliminating the max-of-8-Poisson block tail (~35% of agg time).
__global__ void __launch_bounds__(256)
k_agg(const float* __restrict__ feat) {
    const int lane = threadIdx.x & 31;
    const int hsel = lane & 3;
    const bool b0 = (lane & 1) != 0, b1 = (lane & 2) != 0;
    const int* cp = g_csr_src;

    for (;;) {
        int n;
        if (lane == 0) n = atomicAdd(&g_work, 1);
        n = __shfl_sync(0xffffffffu, n, 0);
        if (n >= NN) return;
        if (lane == 0) g_counts[n] = 0;   // reset for next replay's hist

        const int start = g_offsets[n];
        const int end = g_offsets[n + 1];
        float* zp = g_z + (size_t)n * 512 + lane * 4;

        if (start == end) {
            float4 zz = make_float4(0.f, 0.f, 0.f, 0.f);
#pragma unroll
            for (int h = 0; h < 4; h++) *(float4*)(zp + h * FIN) = zz;
            continue;
        }

        float4 fd = *(const float4*)(feat + n * FIN + lane * 4);
        float4 c0 = *(const float4*)(g_wc + 0 * FIN + lane * 4);
        float4 c1 = *(const float4*)(g_wc + 1 * FIN + lane * 4);
        float4 c2 = *(const float4*)(g_wc + 2 * FIN + lane * 4);
        float4 c3 = *(const float4*)(g_wc + 3 * FIN + lane * 4);
        c0.x *= fd.x; c0.y *= fd.y; c0.z *= fd.z; c0.w *= fd.w;
        c1.x *= fd.x; c1.y *= fd.y; c1.z *= fd.z; c1.w *= fd.w;
        c2.x *= fd.x; c2.y *= fd.y; c2.z *= fd.z; c2.w *= fd.w;
        c3.x *= fd.x; c3.y *= fd.y; c3.z *= fd.z; c3.w *= fd.w;

        // permute once: cq_i = c[hsel ^ i]
        float4 cq0 = b1 ? (b0 ? c3 : c2) : (b0 ? c1 : c0);
        float4 cq1 = b1 ? (b0 ? c2 : c3) : (b0 ? c0 : c1);
        float4 cq2 = b1 ? (b0 ? c1 : c0) : (b0 ? c3 : c2);
        float4 cq3 = b1 ? (b0 ? c0 : c1) : (b0 ? c2 : c3);

        float s = 0.f;
        float4 z0 = make_float4(0.f, 0.f, 0.f, 0.f);
        float4 z1 = z0, z2 = z0, z3 = z0;

#pragma unroll 2
        for (int idx = start; idx < end; ++idx) {
            int src = __ldg(cp + idx);
            float4 fs = *(const float4*)(feat + src * FIN + lane * 4);
            float el = __ldg(g_el2 + src * 4 + hsel);

            float q0 = fs.x * cq0.x + fs.y * cq0.y + fs.z * cq0.z + fs.w * cq0.w;
            float q1 = fs.x * cq1.x + fs.y * cq1.y + fs.z * cq1.z + fs.w * cq1.w;
            float q2 = fs.x * cq2.x + fs.y * cq2.y + fs.z * cq2.z + fs.w * cq2.w;
            float q3 = fs.x * cq3.x + fs.y * cq3.y + fs.z * cq3.z + fs.w * cq3.w;

            float u01 = q0 + __shfl_xor_sync(0xffffffffu, q1, 1);
            float u23 = q2 + __shfl_xor_sync(0xffffffffu, q3, 1);
            float v = u01 + __shfl_xor_sync(0xffffffffu, u23, 2);
            v += __shfl_xor_sync(0xffffffffu, v, 4);
            v += __shfl_xor_sync(0xffffffffu, v, 8);
            v += __shfl_xor_sync(0xffffffffu, v, 16);

            float w = __expf(v + el);
            s += w;

            float w0 = __shfl_sync(0xffffffffu, w, 0);
            float w1 = __shfl_sync(0xffffffffu, w, 1);
            float w2 = __shfl_sync(0xffffffffu, w, 2);
            float w3 = __shfl_sync(0xffffffffu, w, 3);

            z0.x += w0 * fs.x; z0.y += w0 * fs.y; z0.z += w0 * fs.z; z0.w += w0 * fs.w;
            z1.x += w1 * fs.x; z1.y += w1 * fs.y; z1.z += w1 * fs.z; z1.w += w1 * fs.w;
            z2.x += w2 * fs.x; z2.y += w2 * fs.y; z2.z += w2 * fs.z; z2.w += w2 * fs.w;
            z3.x += w3 * fs.x; z3.y += w3 * fs.y; z3.z += w3 * fs.z; z3.w += w3 * fs.w;
        }

        float rinv = 1.f / s;
        float r0 = __shfl_sync(0xffffffffu, rinv, 0);
        float r1 = __shfl_sync(0xffffffffu, rinv, 1);
        float r2 = __shfl_sync(0xffffffffu, rinv, 2);
        float r3 = __shfl_sync(0xffffffffu, rinv, 3);

        *(float4*)(zp + 0 * FIN) = make_float4(z0.x * r0, z0.y * r0, z0.z * r0, z0.w * r0);
        *(float4*)(zp + 1 * FIN) = make_float4(z1.x * r1, z1.y * r1, z1.z * r1, z1.w * r1);
        *(float4*)(zp + 2 * FIN) = make_float4(z2.x * r2, z2.y * r2, z2.z * r2, z2.w * r2);
        *(float4*)(zp + 3 * FIN) = make_float4(z3.x * r3, z3.y * r3, z3.z * r3, z3.w * r3);
    }
}

// ---------------- tensor-core split-tf32 GEMM, split-at-staging ----------------
__global__ void __launch_bounds__(256)
k_tc(const float* __restrict__ bias, float* __restrict__ out) {
    __shared__ float zsh[128][36];
    __shared__ float zsl[128][36];
    const int h = blockIdx.x;
    const int nBase = blockIdx.y * 128;
    const int tid = threadIdx.x;
    const int w = tid >> 5;
    const int lane = tid & 31;
    const int g = lane >> 2;
    const int t4 = lane & 3;
    const int cg = w & 3;
    const int np = w >> 2;

    float acc[8][4];
#pragma unroll
    for (int i = 0; i < 8; i++)
#pragma unroll
        for (int j = 0; j < 4; j++) acc[i][j] = 0.f;

    const float* wh = g_wsh + (size_t)(h * FO + cg * 16) * FIN;
    const float* wl = g_wsl + (size_t)(h * FO + cg * 16) * FIN;

    for (int kc = 0; kc < 4; kc++) {
        __syncthreads();
#pragma unroll
        for (int i = 0; i < 4; i++) {
            int slot = tid + i * 256;
            int row = slot >> 3;
            int c4 = (slot & 7) * 4;
            size_t gi = (size_t)(nBase + row) * 512 + h * 128 + kc * 32 + c4;
            float4 v = *(const float4*)(g_z + gi);
            float4 hi4, lo4;
            hi4.x = tf32_rna(v.x); lo4.x = tf32_rna(v.x - hi4.x);
            hi4.y = tf32_rna(v.y); lo4.y = tf32_rna(v.y - hi4.y);
            hi4.z = tf32_rna(v.z); lo4.z = tf32_rna(v.z - hi4.z);
            hi4.w = tf32_rna(v.w); lo4.w = tf32_rna(v.w - hi4.w);
            *(float4*)(&zsh[row][c4]) = hi4;
            *(float4*)(&zsl[row][c4]) = lo4;
        }
        __syncthreads();

#pragma unroll
        for (int kf = 0; kf < 4; kf++) {
            const int k0 = kc * 32 + kf * 8;
            uint32_t ah0 = __float_as_uint(__ldg(wh + (g)     * FIN + k0 + t4));
            uint32_t ah1 = __float_as_uint(__ldg(wh + (g + 8) * FIN + k0 + t4));
            uint32_t ah2 = __float_as_uint(__ldg(wh + (g)     * FIN + k0 + t4 + 4));
            uint32_t ah3 = __float_as_uint(__ldg(wh + (g + 8) * FIN + k0 + t4 + 4));
            uint32_t al0 = __float_as_uint(__ldg(wl + (g)     * FIN + k0 + t4));
            uint32_t al1 = __float_as_uint(__ldg(wl + (g + 8) * FIN + k0 + t4));
            uint32_t al2 = __float_as_uint(__ldg(wl + (g)     * FIN + k0 + t4 + 4));
            uint32_t al3 = __float_as_uint(__ldg(wl + (g + 8) * FIN + k0 + t4 + 4));
            const int ks = kf * 8;
#pragma unroll
            for (int nf = 0; nf < 8; nf++) {
                int row = np * 64 + nf * 8 + g;
                uint32_t bh0 = __float_as_uint(zsh[row][ks + t4]);
                uint32_t bh1 = __float_as_uint(zsh[row][ks + t4 + 4]);
                uint32_t bl0 = __float_as_uint(zsl[row][ks + t4]);
                uint32_t bl1 = __float_as_uint(zsl[row][ks + t4 + 4]);
                mma_tf32(acc[nf][0], acc[nf][1], acc[nf][2], acc[nf][3],
                         ah0, ah1, ah2, ah3, bh0, bh1);
                mma_tf32(acc[nf][0], acc[nf][1], acc[nf][2], acc[nf][3],
                         ah0, ah1, ah2, ah3, bl0, bl1);
                mma_tf32(acc[nf][0], acc[nf][1], acc[nf][2], acc[nf][3],
                         al0, al1, al2, al3, bh0, bh1);
            }
        }
    }

    int ch  = h * FO + cg * 16 + g;
    int ch8 = ch + 8;
    float bg  = __ldg(bias + ch);
    float bg8 = __ldg(bias + ch8);
#pragma unroll
    for (int nf = 0; nf < 8; nf++) {
        int n0 = nBase + np * 64 + nf * 8 + 2 * t4;
        int n1 = n0 + 1;
        if (n0 < NN) {
            out[(size_t)n0 * NOUT + ch]  = acc[nf][0] + bg;
            out[(size_t)n0 * NOUT + ch8] = acc[nf][2] + bg8;
        }
        if (n1 < NN) {
            out[(size_t)n1 * NOUT + ch]  = acc[nf][1] + bg;
            out[(size_t)n1 * NOUT + ch8] = acc[nf][3] + bg8;
        }
    }
}

// ---------------- launch ----------------
extern "C" void kernel_launch(void* const* d_in, const int* in_sizes, int n_in,
                              void* d_out, int out_size) {
    const float* feat  = (const float*)d_in[0];
    const int*   src   = (const int*)d_in[1];
    const int*   dst   = (const int*)d_in[2];
    const float* fc_w  = (const float*)d_in[3];
    const float* al    = (const float*)d_in[4];
    const float* ar    = (const float*)d_in[5];
    const float* al1   = (const float*)d_in[6];
    const float* ar1   = (const float*)d_in[7];
    const float* bias  = (const float*)d_in[8];
    float* out = (float*)d_out;

    k_front<<<NODE_BLKS + HIST_BLKS + PREP_BLKS, 256>>>(feat, dst, al, ar, al1, ar1, fc_w);
    k_scan<<<SCAN_BLKS, 1024>>>();
    k_scatter<<<(EE / 4 + 255) / 256, 256>>>(src, dst);
    k_agg<<<AGG_BLKS, 256>>>(feat);
    k_tc<<<dim3(HH, NR / 128), 256>>>(bias, out);
}

// round 16
// speedup vs baseline: 1.2261x; 1.2261x over previous
#include <cuda_runtime.h>
#include <cuda_bf16.h>
#include <cstdint>

#define NN 50000
#define NR 50048      // 391 * 128
#define EE 800000
#define FIN 128
#define HH 4
#define FO 64
#define NOUT 256

#define NODE_BLKS 6250   // 50000 warps @ 8 warps/block
#define HIST_BLKS 782    // ceil((EE/4)/256)
#define PREP_BLKS 128    // 32768/256
#define SCAN_BLKS 49     // ceil(NN/1024)

// ---- static scratch ----
__device__ uint32_t g_zph[(size_t)NR * 256]; // z bf16-hi packed pairs [n][h][64] u32
__device__ uint32_t g_zpl[(size_t)NR * 256]; // z bf16-lo packed pairs
__device__ uint32_t g_wph[NOUT * 64];        // W bf16-hi packed pairs [ch][64]
__device__ uint32_t g_wpl[NOUT * 64];        // W bf16-lo packed pairs
__device__ float g_el2[NN * HH];
__device__ float g_wc[HH * FIN];
__device__ int   g_counts[NN];               // zeroed at k_agg head (replay-idempotence)
__device__ int   g_offsets[NN + 1];
__device__ int   g_cursor[NN];
__device__ int   g_csr_src[EE];
__device__ int   g_partial[64];
__device__ int   g_flag[64];                 // zeroed by k_front

// ---- helpers ----
__device__ __forceinline__ uint32_t pack_bf16_hi(float a, float b, float& ra, float& rb) {
    // returns bf16x2(lo=a, hi=b); residuals ra=a-bf16(a), rb=b-bf16(b)
    __nv_bfloat16 ba = __float2bfloat16(a);
    __nv_bfloat16 bb = __float2bfloat16(b);
    ra = a - __bfloat162float(ba);
    rb = b - __bfloat162float(bb);
    return (uint32_t)__bfloat16_as_ushort(ba) | ((uint32_t)__bfloat16_as_ushort(bb) << 16);
}
__device__ __forceinline__ uint32_t pack_bf16(float a, float b) {
    __nv_bfloat16 ba = __float2bfloat16(a);
    __nv_bfloat16 bb = __float2bfloat16(b);
    return (uint32_t)__bfloat16_as_ushort(ba) | ((uint32_t)__bfloat16_as_ushort(bb) << 16);
}
__device__ __forceinline__ void mma_bf16(float& d0, float& d1, float& d2, float& d3,
                                         uint32_t a0, uint32_t a1, uint32_t a2, uint32_t a3,
                                         uint32_t b0, uint32_t b1) {
    asm("mma.sync.aligned.m16n8k16.row.col.f32.bf16.bf16.f32 "
        "{%0,%1,%2,%3}, {%4,%5,%6,%7}, {%8,%9}, {%0,%1,%2,%3};"
        : "+f"(d0), "+f"(d1), "+f"(d2), "+f"(d3)
        : "r"(a0), "r"(a1), "r"(a2), "r"(a3), "r"(b0), "r"(b1));
}

// ---------------- fused front: node-el2 | hist | W-pack+wc+flag-reset ----------------
__global__ void __launch_bounds__(256)
k_front(const float* __restrict__ feat,
        const int* __restrict__ dst,
        const float* __restrict__ al, const float* __restrict__ ar,
        const float* __restrict__ al1, const float* __restrict__ ar1,
        const float* __restrict__ W) {
    int b = blockIdx.x;
    int tid = threadIdx.x;

    if (b < NODE_BLKS) {
        int warp = (b * 256 + tid) >> 5;
        int lane = tid & 31;
        if (warp >= NN) return;
        float4 f = *(const float4*)(feat + warp * FIN + lane * 4);
        float q0 = f.x * f.x, q1 = f.y * f.y, q2 = f.z * f.z, q3 = f.w * f.w;
        float pl[4];
#pragma unroll
        for (int h = 0; h < 4; h++) {
            float4 a = *(const float4*)(al1 + h * FIN + lane * 4);
            pl[h] = q0 * a.x * a.x + q1 * a.y * a.y + q2 * a.z * a.z + q3 * a.w * a.w;
        }
#pragma unroll
        for (int off = 16; off; off >>= 1) {
#pragma unroll
            for (int h = 0; h < 4; h++)
                pl[h] += __shfl_xor_sync(0xffffffffu, pl[h], off);
        }
        if (lane == 0)
            *(float4*)(g_el2 + warp * 4) = make_float4(pl[0], pl[1], pl[2], pl[3]);
    } else if (b < NODE_BLKS + HIST_BLKS) {
        int e4 = ((b - NODE_BLKS) * 256 + tid) * 4;
        if (e4 < EE) {
            int4 d4 = *(const int4*)(dst + e4);
            atomicAdd(&g_counts[d4.x], 1);
            atomicAdd(&g_counts[d4.y], 1);
            atomicAdd(&g_counts[d4.z], 1);
            atomicAdd(&g_counts[d4.w], 1);
        }
    } else {
        int i = (b - NODE_BLKS - HIST_BLKS) * 256 + tid;   // 0..32767
        if (i < NOUT * 64) {    // pack W bf16 hi/lo pairs
            int ch = i >> 6, j = i & 63;
            float w0 = W[ch * FIN + 2 * j];
            float w1 = W[ch * FIN + 2 * j + 1];
            float r0, r1;
            g_wph[i] = pack_bf16_hi(w0, w1, r0, r1);
            g_wpl[i] = pack_bf16(r0, r1);
        }
        if (i < HH * FIN) g_wc[i] = al[i] * ar[i] - 2.0f * al1[i] * ar1[i];
        if (i < 64) g_flag[i] = 0;
    }
}

// ---------------- single-kernel scan (decoupled lookback) ----------------
__global__ void __launch_bounds__(1024)
k_scan() {
    __shared__ int wsum[32];
    __shared__ int s_prefix;
    int tid = threadIdx.x;
    int b = blockIdx.x;
    int t = b * 1024 + tid;
    int lane = tid & 31, wid = tid >> 5;
    int cnt = (t < NN) ? g_counts[t] : 0;
    int x = cnt;
#pragma unroll
    for (int off = 1; off < 32; off <<= 1) {
        int y = __shfl_up_sync(0xffffffffu, x, off);
        if (lane >= off) x += y;
    }
    if (lane == 31) wsum[wid] = x;
    __syncthreads();
    if (wid == 0) {
        int ws = wsum[lane];
#pragma unroll
        for (int off = 1; off < 32; off <<= 1) {
            int y = __shfl_up_sync(0xffffffffu, ws, off);
            if (lane >= off) ws += y;
        }
        wsum[lane] = ws;
    }
    __syncthreads();
    if (wid > 0) x += wsum[wid - 1];
    if (tid == 1023) {
        *((volatile int*)g_partial + b) = x;
        __threadfence();
        atomicExch(&g_flag[b], 1);
    }
    if (wid == 0) {
        int sum = 0;
        for (int i = lane; i < b; i += 32) {
            while (atomicAdd(&g_flag[i], 0) == 0) { }
            sum += *((volatile int*)g_partial + i);
        }
#pragma unroll
        for (int off = 16; off; off >>= 1)
            sum += __shfl_xor_sync(0xffffffffu, sum, off);
        if (lane == 0) s_prefix = sum;
    }
    __syncthreads();
    int inc = x + s_prefix;
    if (t < NN) {
        g_offsets[t + 1] = inc;
        g_cursor[t] = inc - cnt;
    }
    if (t == 0) g_offsets[0] = 0;
}

__global__ void k_scatter(const int* __restrict__ src, const int* __restrict__ dst) {
    int e4 = (blockIdx.x * blockDim.x + threadIdx.x) * 4;
    if (e4 < EE) {
        int4 s4 = *(const int4*)(src + e4);
        int4 d4 = *(const int4*)(dst + e4);
        int p0 = atomicAdd(&g_cursor[d4.x], 1); g_csr_src[p0] = s4.x;
        int p1 = atomicAdd(&g_cursor[d4.y], 1); g_csr_src[p1] = s4.y;
        int p2 = atomicAdd(&g_cursor[d4.z], 1); g_csr_src[p2] = s4.z;
        int p3 = atomicAdd(&g_cursor[d4.w], 1); g_csr_src[p3] = s4.w;
    }
}

// ---------------- fused score + softmax + agg (R14 structure; bf16-packed z output) ----------------
__global__ void __launch_bounds__(256)
k_agg(const float* __restrict__ feat) {
    int gidx = blockIdx.x * blockDim.x + threadIdx.x;
    if (gidx < NN) g_counts[gidx] = 0;   // reset for next replay's hist
    int warp = gidx >> 5;
    int lane = threadIdx.x & 31;
    if (warp >= NN) return;
    const int n = warp;
    const int start = g_offsets[n];
    const int end = g_offsets[n + 1];
    const int hsel = lane & 3;
    uint32_t* zph = g_zph + (size_t)n * 256 + lane * 2;   // pairs 2*lane, 2*lane+1 per head
    uint32_t* zpl = g_zpl + (size_t)n * 256 + lane * 2;

    if (start == end) {
#pragma unroll
        for (int h = 0; h < 4; h++) {
            *(uint2*)(zph + h * 64) = make_uint2(0u, 0u);
            *(uint2*)(zpl + h * 64) = make_uint2(0u, 0u);
        }
        return;
    }

    float4 fd = *(const float4*)(feat + n * FIN + lane * 4);
    float4 c0 = *(const float4*)(g_wc + 0 * FIN + lane * 4);
    float4 c1 = *(const float4*)(g_wc + 1 * FIN + lane * 4);
    float4 c2 = *(const float4*)(g_wc + 2 * FIN + lane * 4);
    float4 c3 = *(const float4*)(g_wc + 3 * FIN + lane * 4);
    c0.x *= fd.x; c0.y *= fd.y; c0.z *= fd.z; c0.w *= fd.w;
    c1.x *= fd.x; c1.y *= fd.y; c1.z *= fd.z; c1.w *= fd.w;
    c2.x *= fd.x; c2.y *= fd.y; c2.z *= fd.z; c2.w *= fd.w;
    c3.x *= fd.x; c3.y *= fd.y; c3.z *= fd.z; c3.w *= fd.w;

    // permute once: cq_i = c[hsel ^ i]
    const bool b0 = (lane & 1) != 0, b1 = (lane & 2) != 0;
    float4 cq0 = b1 ? (b0 ? c3 : c2) : (b0 ? c1 : c0);
    float4 cq1 = b1 ? (b0 ? c2 : c3) : (b0 ? c0 : c1);
    float4 cq2 = b1 ? (b0 ? c1 : c0) : (b0 ? c3 : c2);
    float4 cq3 = b1 ? (b0 ? c0 : c1) : (b0 ? c2 : c3);

    float s = 0.f;
    float4 z0 = make_float4(0.f, 0.f, 0.f, 0.f);
    float4 z1 = z0, z2 = z0, z3 = z0;
    const int* cp = g_csr_src;

#pragma unroll 2
    for (int idx = start; idx < end; ++idx) {
        int src = __ldg(cp + idx);
        float4 fs = *(const float4*)(feat + src * FIN + lane * 4);
        float el = __ldg(g_el2 + src * 4 + hsel);

        float q0 = fs.x * cq0.x + fs.y * cq0.y + fs.z * cq0.z + fs.w * cq0.w;
        float q1 = fs.x * cq1.x + fs.y * cq1.y + fs.z * cq1.z + fs.w * cq1.w;
        float q2 = fs.x * cq2.x + fs.y * cq2.y + fs.z * cq2.z + fs.w * cq2.w;
        float q3 = fs.x * cq3.x + fs.y * cq3.y + fs.z * cq3.z + fs.w * cq3.w;

        float u01 = q0 + __shfl_xor_sync(0xffffffffu, q1, 1);
        float u23 = q2 + __shfl_xor_sync(0xffffffffu, q3, 1);
        float v = u01 + __shfl_xor_sync(0xffffffffu, u23, 2);
        v += __shfl_xor_sync(0xffffffffu, v, 4);
        v += __shfl_xor_sync(0xffffffffu, v, 8);
        v += __shfl_xor_sync(0xffffffffu, v, 16);

        float w = __expf(v + el);
        s += w;

        float w0 = __shfl_sync(0xffffffffu, w, 0);
        float w1 = __shfl_sync(0xffffffffu, w, 1);
        float w2 = __shfl_sync(0xffffffffu, w, 2);
        float w3 = __shfl_sync(0xffffffffu, w, 3);

        z0.x += w0 * fs.x; z0.y += w0 * fs.y; z0.z += w0 * fs.z; z0.w += w0 * fs.w;
        z1.x += w1 * fs.x; z1.y += w1 * fs.y; z1.z += w1 * fs.z; z1.w += w1 * fs.w;
        z2.x += w2 * fs.x; z2.y += w2 * fs.y; z2.z += w2 * fs.z; z2.w += w2 * fs.w;
        z3.x += w3 * fs.x; z3.y += w3 * fs.y; z3.z += w3 * fs.z; z3.w += w3 * fs.w;
    }

    float rinv = 1.f / s;
    float r0 = __shfl_sync(0xffffffffu, rinv, 0);
    float r1 = __shfl_sync(0xffffffffu, rinv, 1);
    float r2 = __shfl_sync(0xffffffffu, rinv, 2);
    float r3 = __shfl_sync(0xffffffffu, rinv, 3);

    float4 zz[4];
    zz[0] = make_float4(z0.x * r0, z0.y * r0, z0.z * r0, z0.w * r0);
    zz[1] = make_float4(z1.x * r1, z1.y * r1, z1.z * r1, z1.w * r1);
    zz[2] = make_float4(z2.x * r2, z2.y * r2, z2.z * r2, z2.w * r2);
    zz[3] = make_float4(z3.x * r3, z3.y * r3, z3.z * r3, z3.w * r3);
#pragma unroll
    for (int h = 0; h < 4; h++) {
        float ra, rb, rc, rd;
        uint32_t h0 = pack_bf16_hi(zz[h].x, zz[h].y, ra, rb);
        uint32_t h1 = pack_bf16_hi(zz[h].z, zz[h].w, rc, rd);
        uint32_t l0 = pack_bf16(ra, rb);
        uint32_t l1 = pack_bf16(rc, rd);
        *(uint2*)(zph + h * 64) = make_uint2(h0, h1);
        *(uint2*)(zpl + h * 64) = make_uint2(l0, l1);
    }
}

// ---------------- tensor-core split-bf16 GEMM (m16n8k16, 3 passes) ----------------
// grid (HH, 391), block 256 (8 warps). Warp w: channels (w&3)*16, node panel (w>>2)*64.
// z staged as raw packed u32 (no cvt); K in 2 chunks of 64 (32 u32).
__global__ void __launch_bounds__(256)
k_tc(const float* __restrict__ bias, float* __restrict__ out) {
    __shared__ uint32_t zsh[128][36];
    __shared__ uint32_t zsl[128][36];
    const int h = blockIdx.x;
    const int nBase = blockIdx.y * 128;
    const int tid = threadIdx.x;
    const int w = tid >> 5;
    const int lane = tid & 31;
    const int g = lane >> 2;
    const int t4 = lane & 3;
    const int cg = w & 3;
    const int np = w >> 2;

    float acc[8][4];
#pragma unroll
    for (int i = 0; i < 8; i++)
#pragma unroll
        for (int j = 0; j < 4; j++) acc[i][j] = 0.f;

    const uint32_t* wh = g_wph + (size_t)(h * FO + cg * 16) * 64;
    const uint32_t* wl = g_wpl + (size_t)(h * FO + cg * 16) * 64;

    for (int kc = 0; kc < 2; kc++) {
        __syncthreads();
#pragma unroll
        for (int i = 0; i < 4; i++) {
            int slot = tid + i * 256;          // 0..1023
            int row = slot >> 3;
            int c4 = (slot & 7) * 4;
            size_t gi = (size_t)(nBase + row) * 256 + h * 64 + kc * 32 + c4;
            *(uint4*)(&zsh[row][c4]) = *(const uint4*)(g_zph + gi);
            *(uint4*)(&zsl[row][c4]) = *(const uint4*)(g_zpl + gi);
        }
        __syncthreads();

#pragma unroll
        for (int kf = 0; kf < 4; kf++) {
            const int jw = (kc * 4 + kf) * 8;     // W pair index base for this k16
            uint32_t ah0 = __ldg(wh + (g)     * 64 + jw + t4);
            uint32_t ah1 = __ldg(wh + (g + 8) * 64 + jw + t4);
            uint32_t ah2 = __ldg(wh + (g)     * 64 + jw + t4 + 4);
            uint32_t ah3 = __ldg(wh + (g + 8) * 64 + jw + t4 + 4);
            uint32_t al0 = __ldg(wl + (g)     * 64 + jw + t4);
            uint32_t al1 = __ldg(wl + (g + 8) * 64 + jw + t4);
            uint32_t al2 = __ldg(wl + (g)     * 64 + jw + t4 + 4);
            uint32_t al3 = __ldg(wl + (g + 8) * 64 + jw + t4 + 4);
            const int js = kf * 8;                // smem pair index within chunk
#pragma unroll
            for (int nf = 0; nf < 8; nf++) {
                int row = np * 64 + nf * 8 + g;
                uint32_t bh0 = zsh[row][js + t4];
                uint32_t bh1 = zsh[row][js + t4 + 4];
                uint32_t bl0 = zsl[row][js + t4];
                uint32_t bl1 = zsl[row][js + t4 + 4];
                mma_bf16(acc[nf][0], acc[nf][1], acc[nf][2], acc[nf][3],
                         ah0, ah1, ah2, ah3, bh0, bh1);
                mma_bf16(acc[nf][0], acc[nf][1], acc[nf][2], acc[nf][3],
                         ah0, ah1, ah2, ah3, bl0, bl1);
                mma_bf16(acc[nf][0], acc[nf][1], acc[nf][2], acc[nf][3],
                         al0, al1, al2, al3, bh0, bh1);
            }
        }
    }

    // D layout (m16n8): c0=(g,2t4), c1=(g,2t4+1), c2=(g+8,2t4), c3=(g+8,2t4+1)
    int ch  = h * FO + cg * 16 + g;
    int ch8 = ch + 8;
    float bg  = __ldg(bias + ch);
    float bg8 = __ldg(bias + ch8);
#pragma unroll
    for (int nf = 0; nf < 8; nf++) {
        int n0 = nBase + np * 64 + nf * 8 + 2 * t4;
        int n1 = n0 + 1;
        if (n0 < NN) {
            out[(size_t)n0 * NOUT + ch]  = acc[nf][0] + bg;
            out[(size_t)n0 * NOUT + ch8] = acc[nf][2] + bg8;
        }
        if (n1 < NN) {
            out[(size_t)n1 * NOUT + ch]  = acc[nf][1] + bg;
            out[(size_t)n1 * NOUT + ch8] = acc[nf][3] + bg8;
        }
    }
}

// ---------------- launch ----------------
extern "C" void kernel_launch(void* const* d_in, const int* in_sizes, int n_in,
                              void* d_out, int out_size) {
    const float* feat  = (const float*)d_in[0];
    const int*   src   = (const int*)d_in[1];
    const int*   dst   = (const int*)d_in[2];
    const float* fc_w  = (const float*)d_in[3];
    const float* al    = (const float*)d_in[4];
    const float* ar    = (const float*)d_in[5];
    const float* al1   = (const float*)d_in[6];
    const float* ar1   = (const float*)d_in[7];
    const float* bias  = (const float*)d_in[8];
    float* out = (float*)d_out;

    k_front<<<NODE_BLKS + HIST_BLKS + PREP_BLKS, 256>>>(feat, dst, al, ar, al1, ar1, fc_w);
    k_scan<<<SCAN_BLKS, 1024>>>();
    k_scatter<<<(EE / 4 + 255) / 256, 256>>>(src, dst);
    k_agg<<<(NN * 32 + 255) / 256, 256>>>(feat);
    k_tc<<<dim3(HH, NR / 128), 256>>>(bias, out);
}

// round 17
// speedup vs baseline: 1.2626x; 1.0297x over previous
#include <cuda_runtime.h>
#include <cuda_bf16.h>
#include <cstdint>

#define NN 50000
#define NR 50048      // 391 * 128
#define EE 800000
#define FIN 128
#define HH 4
#define FO 64
#define NOUT 256

#define NODE_BLKS 6250   // 50000 warps @ 8 warps/block
#define HIST_BLKS 782    // ceil((EE/4)/256)
#define PREP_BLKS 128    // 32768/256
#define SCAN_BLKS 49     // ceil(NN/1024)

// ---- static scratch ----
__device__ uint32_t g_zph[(size_t)NR * 256]; // z bf16-hi packed pairs [n][h][64] u32
__device__ uint32_t g_zpl[(size_t)NR * 256]; // z bf16-lo packed pairs
__device__ uint32_t g_wph[NOUT * 64];        // W bf16-hi packed pairs [ch][64]
__device__ uint32_t g_wpl[NOUT * 64];        // W bf16-lo packed pairs
__device__ float g_el2[NN * HH];
__device__ float g_wc[HH * FIN];
__device__ int   g_counts[NN];               // zeroed at k_agg head (replay-idempotence)
__device__ int   g_offsets[NN + 1];
__device__ int   g_cursor[NN];
__device__ int   g_csr_src[EE];
__device__ int   g_partial[64];
__device__ int   g_flag[64];                 // zeroed by k_front

// ---- helpers ----
__device__ __forceinline__ uint32_t pack_bf16_hi(float a, float b, float& ra, float& rb) {
    __nv_bfloat16 ba = __float2bfloat16(a);
    __nv_bfloat16 bb = __float2bfloat16(b);
    ra = a - __bfloat162float(ba);
    rb = b - __bfloat162float(bb);
    return (uint32_t)__bfloat16_as_ushort(ba) | ((uint32_t)__bfloat16_as_ushort(bb) << 16);
}
__device__ __forceinline__ uint32_t pack_bf16(float a, float b) {
    __nv_bfloat16 ba = __float2bfloat16(a);
    __nv_bfloat16 bb = __float2bfloat16(b);
    return (uint32_t)__bfloat16_as_ushort(ba) | ((uint32_t)__bfloat16_as_ushort(bb) << 16);
}
__device__ __forceinline__ void mma_bf16(float& d0, float& d1, float& d2, float& d3,
                                         uint32_t a0, uint32_t a1, uint32_t a2, uint32_t a3,
                                         uint32_t b0, uint32_t b1) {
    asm("mma.sync.aligned.m16n8k16.row.col.f32.bf16.bf16.f32 "
        "{%0,%1,%2,%3}, {%4,%5,%6,%7}, {%8,%9}, {%0,%1,%2,%3};"
        : "+f"(d0), "+f"(d1), "+f"(d2), "+f"(d3)
        : "r"(a0), "r"(a1), "r"(a2), "r"(a3), "r"(b0), "r"(b1));
}

// ---------------- fused front: node-el2 | hist | W-pack+wc+flag-reset ----------------
__global__ void __launch_bounds__(256)
k_front(const float* __restrict__ feat,
        const int* __restrict__ dst,
        const float* __restrict__ al, const float* __restrict__ ar,
        const float* __restrict__ al1, const float* __restrict__ ar1,
        const float* __restrict__ W) {
    int b = blockIdx.x;
    int tid = threadIdx.x;

    if (b < NODE_BLKS) {
        int warp = (b * 256 + tid) >> 5;
        int lane = tid & 31;
        if (warp >= NN) return;
        float4 f = *(const float4*)(feat + warp * FIN + lane * 4);
        float q0 = f.x * f.x, q1 = f.y * f.y, q2 = f.z * f.z, q3 = f.w * f.w;
        float pl[4];
#pragma unroll
        for (int h = 0; h < 4; h++) {
            float4 a = *(const float4*)(al1 + h * FIN + lane * 4);
            pl[h] = q0 * a.x * a.x + q1 * a.y * a.y + q2 * a.z * a.z + q3 * a.w * a.w;
        }
#pragma unroll
        for (int off = 16; off; off >>= 1) {
#pragma unroll
            for (int h = 0; h < 4; h++)
                pl[h] += __shfl_xor_sync(0xffffffffu, pl[h], off);
        }
        if (lane == 0)
            *(float4*)(g_el2 + warp * 4) = make_float4(pl[0], pl[1], pl[2], pl[3]);
    } else if (b < NODE_BLKS + HIST_BLKS) {
        int e4 = ((b - NODE_BLKS) * 256 + tid) * 4;
        if (e4 < EE) {
            int4 d4 = *(const int4*)(dst + e4);
            atomicAdd(&g_counts[d4.x], 1);
            atomicAdd(&g_counts[d4.y], 1);
            atomicAdd(&g_counts[d4.z], 1);
            atomicAdd(&g_counts[d4.w], 1);
        }
    } else {
        int i = (b - NODE_BLKS - HIST_BLKS) * 256 + tid;   // 0..32767
        if (i < NOUT * 64) {    // pack W bf16 hi/lo pairs
            int ch = i >> 6, j = i & 63;
            float w0 = W[ch * FIN + 2 * j];
            float w1 = W[ch * FIN + 2 * j + 1];
            float r0, r1;
            g_wph[i] = pack_bf16_hi(w0, w1, r0, r1);
            g_wpl[i] = pack_bf16(r0, r1);
        }
        if (i < HH * FIN) g_wc[i] = al[i] * ar[i] - 2.0f * al1[i] * ar1[i];
        if (i < 64) g_flag[i] = 0;
    }
}

// ---------------- single-kernel scan (decoupled lookback) ----------------
__global__ void __launch_bounds__(1024)
k_scan() {
    __shared__ int wsum[32];
    __shared__ int s_prefix;
    int tid = threadIdx.x;
    int b = blockIdx.x;
    int t = b * 1024 + tid;
    int lane = tid & 31, wid = tid >> 5;
    int cnt = (t < NN) ? g_counts[t] : 0;
    int x = cnt;
#pragma unroll
    for (int off = 1; off < 32; off <<= 1) {
        int y = __shfl_up_sync(0xffffffffu, x, off);
        if (lane >= off) x += y;
    }
    if (lane == 31) wsum[wid] = x;
    __syncthreads();
    if (wid == 0) {
        int ws = wsum[lane];
#pragma unroll
        for (int off = 1; off < 32; off <<= 1) {
            int y = __shfl_up_sync(0xffffffffu, ws, off);
            if (lane >= off) ws += y;
        }
        wsum[lane] = ws;
    }
    __syncthreads();
    if (wid > 0) x += wsum[wid - 1];
    if (tid == 1023) {
        *((volatile int*)g_partial + b) = x;
        __threadfence();
        atomicExch(&g_flag[b], 1);
    }
    if (wid == 0) {
        int sum = 0;
        for (int i = lane; i < b; i += 32) {
            while (atomicAdd(&g_flag[i], 0) == 0) { }
            sum += *((volatile int*)g_partial + i);
        }
#pragma unroll
        for (int off = 16; off; off >>= 1)
            sum += __shfl_xor_sync(0xffffffffu, sum, off);
        if (lane == 0) s_prefix = sum;
    }
    __syncthreads();
    int inc = x + s_prefix;
    if (t < NN) {
        g_offsets[t + 1] = inc;
        g_cursor[t] = inc - cnt;
    }
    if (t == 0) g_offsets[0] = 0;
}

__global__ void k_scatter(const int* __restrict__ src, const int* __restrict__ dst) {
    int e4 = (blockIdx.x * blockDim.x + threadIdx.x) * 4;
    if (e4 < EE) {
        int4 s4 = *(const int4*)(src + e4);
        int4 d4 = *(const int4*)(dst + e4);
        int p0 = atomicAdd(&g_cursor[d4.x], 1); g_csr_src[p0] = s4.x;
        int p1 = atomicAdd(&g_cursor[d4.y], 1); g_csr_src[p1] = s4.y;
        int p2 = atomicAdd(&g_cursor[d4.z], 1); g_csr_src[p2] = s4.z;
        int p3 = atomicAdd(&g_cursor[d4.w], 1); g_csr_src[p3] = s4.w;
    }
}

// ---------------- fused score + softmax + agg ----------------
// Chunked CSR index prefetch: 32 indices loaded per coalesced LDG (one/lane),
// distributed by shfl -> the per-edge serial chain starts at the fs load.
__global__ void __launch_bounds__(256)
k_agg(const float* __restrict__ feat) {
    int gidx = blockIdx.x * blockDim.x + threadIdx.x;
    if (gidx < NN) g_counts[gidx] = 0;   // reset for next replay's hist
    int warp = gidx >> 5;
    int lane = threadIdx.x & 31;
    if (warp >= NN) return;
    const int n = warp;
    const int start = g_offsets[n];
    const int end = g_offsets[n + 1];
    const int hsel = lane & 3;
    uint32_t* zph = g_zph + (size_t)n * 256 + lane * 2;
    uint32_t* zpl = g_zpl + (size_t)n * 256 + lane * 2;

    if (start == end) {
#pragma unroll
        for (int h = 0; h < 4; h++) {
            *(uint2*)(zph + h * 64) = make_uint2(0u, 0u);
            *(uint2*)(zpl + h * 64) = make_uint2(0u, 0u);
        }
        return;
    }

    float4 fd = *(const float4*)(feat + n * FIN + lane * 4);
    float4 c0 = *(const float4*)(g_wc + 0 * FIN + lane * 4);
    float4 c1 = *(const float4*)(g_wc + 1 * FIN + lane * 4);
    float4 c2 = *(const float4*)(g_wc + 2 * FIN + lane * 4);
    float4 c3 = *(const float4*)(g_wc + 3 * FIN + lane * 4);
    c0.x *= fd.x; c0.y *= fd.y; c0.z *= fd.z; c0.w *= fd.w;
    c1.x *= fd.x; c1.y *= fd.y; c1.z *= fd.z; c1.w *= fd.w;
    c2.x *= fd.x; c2.y *= fd.y; c2.z *= fd.z; c2.w *= fd.w;
    c3.x *= fd.x; c3.y *= fd.y; c3.z *= fd.z; c3.w *= fd.w;

    // permute once: cq_i = c[hsel ^ i]
    const bool b0 = (lane & 1) != 0, b1 = (lane & 2) != 0;
    float4 cq0 = b1 ? (b0 ? c3 : c2) : (b0 ? c1 : c0);
    float4 cq1 = b1 ? (b0 ? c2 : c3) : (b0 ? c0 : c1);
    float4 cq2 = b1 ? (b0 ? c1 : c0) : (b0 ? c3 : c2);
    float4 cq3 = b1 ? (b0 ? c0 : c1) : (b0 ? c2 : c3);

    float s = 0.f;
    float4 z0 = make_float4(0.f, 0.f, 0.f, 0.f);
    float4 z1 = z0, z2 = z0, z3 = z0;
    const int* cp = g_csr_src;

    for (int base = start; base < end; base += 32) {
        const int nchunk = min(32, end - base);
        int myi = (base + lane < end) ? __ldg(cp + base + lane) : 0;

#pragma unroll 2
        for (int e = 0; e < nchunk; ++e) {
            int src = __shfl_sync(0xffffffffu, myi, e);
            float4 fs = *(const float4*)(feat + src * FIN + lane * 4);
            float el = __ldg(g_el2 + src * 4 + hsel);

            float q0 = fs.x * cq0.x + fs.y * cq0.y + fs.z * cq0.z + fs.w * cq0.w;
            float q1 = fs.x * cq1.x + fs.y * cq1.y + fs.z * cq1.z + fs.w * cq1.w;
            float q2 = fs.x * cq2.x + fs.y * cq2.y + fs.z * cq2.z + fs.w * cq2.w;
            float q3 = fs.x * cq3.x + fs.y * cq3.y + fs.z * cq3.z + fs.w * cq3.w;

            float u01 = q0 + __shfl_xor_sync(0xffffffffu, q1, 1);
            float u23 = q2 + __shfl_xor_sync(0xffffffffu, q3, 1);
            float v = u01 + __shfl_xor_sync(0xffffffffu, u23, 2);
            v += __shfl_xor_sync(0xffffffffu, v, 4);
            v += __shfl_xor_sync(0xffffffffu, v, 8);
            v += __shfl_xor_sync(0xffffffffu, v, 16);

            float w = __expf(v + el);
            s += w;

            float w0 = __shfl_sync(0xffffffffu, w, 0);
            float w1 = __shfl_sync(0xffffffffu, w, 1);
            float w2 = __shfl_sync(0xffffffffu, w, 2);
            float w3 = __shfl_sync(0xffffffffu, w, 3);

            z0.x += w0 * fs.x; z0.y += w0 * fs.y; z0.z += w0 * fs.z; z0.w += w0 * fs.w;
            z1.x += w1 * fs.x; z1.y += w1 * fs.y; z1.z += w1 * fs.z; z1.w += w1 * fs.w;
            z2.x += w2 * fs.x; z2.y += w2 * fs.y; z2.z += w2 * fs.z; z2.w += w2 * fs.w;
            z3.x += w3 * fs.x; z3.y += w3 * fs.y; z3.z += w3 * fs.z; z3.w += w3 * fs.w;
        }
    }

    float rinv = 1.f / s;
    float r0 = __shfl_sync(0xffffffffu, rinv, 0);
    float r1 = __shfl_sync(0xffffffffu, rinv, 1);
    float r2 = __shfl_sync(0xffffffffu, rinv, 2);
    float r3 = __shfl_sync(0xffffffffu, rinv, 3);

    float4 zz[4];
    zz[0] = make_float4(z0.x * r0, z0.y * r0, z0.z * r0, z0.w * r0);
    zz[1] = make_float4(z1.x * r1, z1.y * r1, z1.z * r1, z1.w * r1);
    zz[2] = make_float4(z2.x * r2, z2.y * r2, z2.z * r2, z2.w * r2);
    zz[3] = make_float4(z3.x * r3, z3.y * r3, z3.z * r3, z3.w * r3);
#pragma unroll
    for (int h = 0; h < 4; h++) {
        float ra, rb, rc, rd;
        uint32_t h0 = pack_bf16_hi(zz[h].x, zz[h].y, ra, rb);
        uint32_t h1 = pack_bf16_hi(zz[h].z, zz[h].w, rc, rd);
        uint32_t l0 = pack_bf16(ra, rb);
        uint32_t l1 = pack_bf16(rc, rd);
        *(uint2*)(zph + h * 64) = make_uint2(h0, h1);
        *(uint2*)(zpl + h * 64) = make_uint2(l0, l1);
    }
}

// ---------------- tensor-core split-bf16 GEMM (m16n8k16, 3 passes) ----------------
__global__ void __launch_bounds__(256)
k_tc(const float* __restrict__ bias, float* __restrict__ out) {
    __shared__ uint32_t zsh[128][36];
    __shared__ uint32_t zsl[128][36];
    const int h = blockIdx.x;
    const int nBase = blockIdx.y * 128;
    const int tid = threadIdx.x;
    const int w = tid >> 5;
    const int lane = tid & 31;
    const int g = lane >> 2;
    const int t4 = lane & 3;
    const int cg = w & 3;
    const int np = w >> 2;

    float acc[8][4];
#pragma unroll
    for (int i = 0; i < 8; i++)
#pragma unroll
        for (int j = 0; j < 4; j++) acc[i][j] = 0.f;

    const uint32_t* wh = g_wph + (size_t)(h * FO + cg * 16) * 64;
    const uint32_t* wl = g_wpl + (size_t)(h * FO + cg * 16) * 64;

    for (int kc = 0; kc < 2; kc++) {
        __syncthreads();
#pragma unroll
        for (int i = 0; i < 4; i++) {
            int slot = tid + i * 256;          // 0..1023
            int row = slot >> 3;
            int c4 = (slot & 7) * 4;
            size_t gi = (size_t)(nBase + row) * 256 + h * 64 + kc * 32 + c4;
            *(uint4*)(&zsh[row][c4]) = *(const uint4*)(g_zph + gi);
            *(uint4*)(&zsl[row][c4]) = *(const uint4*)(g_zpl + gi);
        }
        __syncthreads();

#pragma unroll
        for (int kf = 0; kf < 4; kf++) {
            const int jw = (kc * 4 + kf) * 8;
            uint32_t ah0 = __ldg(wh + (g)     * 64 + jw + t4);
            uint32_t ah1 = __ldg(wh + (g + 8) * 64 + jw + t4);
            uint32_t ah2 = __ldg(wh + (g)     * 64 + jw + t4 + 4);
            uint32_t ah3 = __ldg(wh + (g + 8) * 64 + jw + t4 + 4);
            uint32_t al0 = __ldg(wl + (g)     * 64 + jw + t4);
            uint32_t al1 = __ldg(wl + (g + 8) * 64 + jw + t4);
            uint32_t al2 = __ldg(wl + (g)     * 64 + jw + t4 + 4);
            uint32_t al3 = __ldg(wl + (g + 8) * 64 + jw + t4 + 4);
            const int js = kf * 8;
#pragma unroll
            for (int nf = 0; nf < 8; nf++) {
                int row = np * 64 + nf * 8 + g;
                uint32_t bh0 = zsh[row][js + t4];
                uint32_t bh1 = zsh[row][js + t4 + 4];
                uint32_t bl0 = zsl[row][js + t4];
                uint32_t bl1 = zsl[row][js + t4 + 4];
                mma_bf16(acc[nf][0], acc[nf][1], acc[nf][2], acc[nf][3],
                         ah0, ah1, ah2, ah3, bh0, bh1);
                mma_bf16(acc[nf][0], acc[nf][1], acc[nf][2], acc[nf][3],
                         ah0, ah1, ah2, ah3, bl0, bl1);
                mma_bf16(acc[nf][0], acc[nf][1], acc[nf][2], acc[nf][3],
                         al0, al1, al2, al3, bh0, bh1);
            }
        }
    }

    int ch  = h * FO + cg * 16 + g;
    int ch8 = ch + 8;
    float bg  = __ldg(bias + ch);
    float bg8 = __ldg(bias + ch8);
#pragma unroll
    for (int nf = 0; nf < 8; nf++) {
        int n0 = nBase + np * 64 + nf * 8 + 2 * t4;
        int n1 = n0 + 1;
        if (n0 < NN) {
            out[(size_t)n0 * NOUT + ch]  = acc[nf][0] + bg;
            out[(size_t)n0 * NOUT + ch8] = acc[nf][2] + bg8;
        }
        if (n1 < NN) {
            out[(size_t)n1 * NOUT + ch]  = acc[nf][1] + bg;
            out[(size_t)n1 * NOUT + ch8] = acc[nf][3] + bg8;
        }
    }
}

// ---------------- launch ----------------
extern "C" void kernel_launch(void* const* d_in, const int* in_sizes, int n_in,
                              void* d_out, int out_size) {
    const float* feat  = (const float*)d_in[0];
    const int*   src   = (const int*)d_in[1];
    const int*   dst   = (const int*)d_in[2];
    const float* fc_w  = (const float*)d_in[3];
    const float* al    = (const float*)d_in[4];
    const float* ar    = (const float*)d_in[5];
    const float* al1   = (const float*)d_in[6];
    const float* ar1   = (const float*)d_in[7];
    const float* bias  = (const float*)d_in[8];
    float* out = (float*)d_out;

    k_front<<<NODE_BLKS + HIST_BLKS + PREP_BLKS, 256>>>(feat, dst, al, ar, al1, ar1, fc_w);
    k_scan<<<SCAN_BLKS, 1024>>>();
    k_scatter<<<(EE / 4 + 255) / 256, 256>>>(src, dst);
    k_agg<<<(NN * 32 + 255) / 256, 256>>>(feat);
    k_tc<<<dim3(HH, NR / 128), 256>>>(bias, out);
}